// round 7
// baseline (speedup 1.0000x reference)
#include <cuda_runtime.h>

#define HH 512
#define WW 512
#define NB 8
#define HID 64
#define TH 0.012271846303085129f   // 2*pi/512
#define INV_N2 3.814697265625e-06f // 1/(512*512)

typedef unsigned long long u64;

// ---------------- scratch (static device globals; no allocation) -------------
__device__ float  g_R2[16 * NB * HH];     // [v][b*512+h], v = 2*ky + (0:re / 1:im)
__device__ float2 g_Z[NB * HID * 8 * 8];  // [b][j][ky][kx]
__device__ float  g_alpha[HID];
__device__ float  g_beta[HID];

// ---------------- f32x2 packed helpers ---------------------------------------
__device__ __forceinline__ u64 pk2(float lo, float hi) {
    u64 r; asm("mov.b64 %0, {%1,%2};" : "=l"(r) : "f"(lo), "f"(hi)); return r;
}
__device__ __forceinline__ void upk2(u64 v, float& lo, float& hi) {
    asm("mov.b64 {%0,%1}, %2;" : "=f"(lo), "=f"(hi) : "l"(v));
}
__device__ __forceinline__ u64 fma2(u64 a, u64 b, u64 c) {
    u64 d; asm("fma.rn.f32x2 %0, %1, %2, %3;" : "=l"(d) : "l"(a), "l"(b), "l"(c)); return d;
}
__device__ __forceinline__ u64 mul2(u64 a, u64 b) {
    u64 d; asm("mul.rn.f32x2 %0, %1, %2;" : "=l"(d) : "l"(a), "l"(b)); return d;
}
__device__ __forceinline__ u64 add2(u64 a, u64 b) {
    u64 d; asm("add.rn.f32x2 %0, %1, %2;" : "=l"(d) : "l"(a), "l"(b)); return d;
}

// ============ stage 1: per-row partial DFT of x (8 modes, +-256 folded) =======
__global__ void __launch_bounds__(256) k_rowdft(const float* __restrict__ x) {
    const int b = blockIdx.y, h = blockIdx.x;
    const int tid = threadIdx.x;

    __shared__ float sv[256 * 17];
    __shared__ float sp[16 * 17];

    const float* row = x + ((size_t)b * HH + h) * WW;
    float xs = row[tid] + row[tid + 256];
    float xd = row[tid] - row[tid + 256];

    float vals[16];
    {
        float s1, c1;
        __sincosf((float)tid * TH, &s1, &c1);
        float ck = 1.f, sk = 0.f;
#pragma unroll
        for (int k = 0; k < 8; k++) {
            float src = (k & 1) ? xd : xs;
            vals[2 * k]     =  src * ck;
            vals[2 * k + 1] = -src * sk;
            float cn = ck * c1 - sk * s1;
            float sn = sk * c1 + ck * s1;
            ck = cn; sk = sn;
        }
    }

#pragma unroll
    for (int i = 0; i < 16; i++) sv[tid * 17 + i] = vals[i];
    __syncthreads();

    // partial reduce: thread t -> (v = t&15, g = t>>4) sums 16 rows
    {
        int v = tid & 15, g = tid >> 4;
        float p = 0.f;
#pragma unroll
        for (int i = 0; i < 16; i++) p += sv[(g * 16 + i) * 17 + v];
        sp[g * 17 + v] = p;
    }
    __syncthreads();

    if (tid < 16) {
        float s = 0.f;
#pragma unroll
        for (int g = 0; g < 16; g++) s += sp[g * 17 + tid];
        g_R2[tid * (NB * HH) + b * HH + h] = s;
    }
}

// ============ stage 2: fused column-DFT + mode chain + affine =================
// 64 blocks (site = kx*8+ky), 128 threads (b = t>>4, o = t&15).
__global__ void __launch_bounds__(128) k_spectral(const float* __restrict__ spec_wr,
                                                  const float* __restrict__ spec_wi,
                                                  const float* __restrict__ conv_w,
                                                  const float* __restrict__ conv_b,
                                                  const float* __restrict__ fc0_w,
                                                  const float* __restrict__ fc0_b,
                                                  const float* __restrict__ fc1_w,
                                                  const float* __restrict__ fc1_b) {
    const int site = blockIdx.x;
    const int kx = site >> 3, ky = site & 7;
    const bool dc = (site == 0);
    const int t = threadIdx.x;
    const int b = t >> 4, o = t & 15;

    __shared__ float swr[768];     // [d][c][o] linear
    __shared__ float swi[768];
    __shared__ float scw[768];     // conv_w [d][o][c] linear
    __shared__ float sfc1[1024];   // fc1_w  [o][j]  linear
    __shared__ float sXr[NB], sXi[NB];
    __shared__ float2 X[NB][16], Y0[NB][16], Y1[NB][16], Y2[NB][16];

    // -- phase A: issue scattered weight loads into registers (overlap w/ DFT) --
    float rwr[6], rwi[6], rcw[6], rf1[8];
#pragma unroll
    for (int q = 0; q < 6; q++) {
        int i = t + 128 * q;
        rwr[q] = spec_wr[(size_t)i * 64 + site];
        rwi[q] = spec_wi[(size_t)i * 64 + site];
        rcw[q] = conv_w[i];
    }
#pragma unroll
    for (int q = 0; q < 8; q++) rf1[q] = fc1_w[t + 128 * q];

    if (t < NB) { sXr[t] = 0.f; sXi[t] = 0.f; }
    __syncthreads();

    // -- phase B: column DFT for this (kx,ky): Xx(b) = sum_h R(b,h,ky) e^{-i kx th h}
    {
        const int chunk = t & 15;
        const float* pr = g_R2 + (2 * ky) * (NB * HH) + b * HH;
        const float* pim = g_R2 + (2 * ky + 1) * (NB * HH) + b * HH;
        float c0, s0, cs, ss;
        __sincosf((float)kx * TH * (float)chunk, &s0, &c0);
        __sincosf((float)kx * TH * 16.f, &ss, &cs);
        float ck = c0, sk = s0;
        float vr = 0.f, vi = 0.f;
#pragma unroll 4
        for (int it = 0; it < 32; it++) {
            int h = chunk + 16 * it;
            float rr = pr[h], ri = pim[h];
            vr += rr * ck + ri * sk;
            vi += ri * ck - rr * sk;
            float cn = ck * cs - sk * ss;
            float sn = sk * cs + ck * ss;
            ck = cn; sk = sn;
        }
        atomicAdd(&sXr[b], vr);
        atomicAdd(&sXi[b], vi);
    }

    // -- stage weights to smem --
#pragma unroll
    for (int q = 0; q < 6; q++) {
        int i = t + 128 * q;
        swr[i] = rwr[q];
        swi[i] = rwi[q];
        scw[i] = rcw[q];
    }
#pragma unroll
    for (int q = 0; q < 8; q++) sfc1[t + 128 * q] = rf1[q];
    __syncthreads();

    // -- alpha/beta (site 0, warp 0 only; shuffle-based, no extra syncs) --
    if (dc && t < 32) {
        int oo = t & 15;
        float v = fc0_w[oo], bbv = fc0_b[oo];
        for (int d = 0; d < 3; d++) {
            float sv_ = 0.f, sb_ = 0.f;
#pragma unroll
            for (int c = 0; c < 16; c++) {
                float vv = __shfl_sync(0xffffffffu, v, c);
                float bv = __shfl_sync(0xffffffffu, bbv, c);
                float cw = scw[d * 256 + oo * 16 + c];
                sv_ += cw * vv;
                sb_ += cw * bv;
            }
            v = sv_;
            bbv = sb_ + conv_b[d * 16 + oo];
        }
        for (int jj = t; jj < 64; jj += 32) {
            float a = 0.f, be = 0.f;
#pragma unroll
            for (int o2 = 0; o2 < 16; o2++) {
                float vv = __shfl_sync(0xffffffffu, v, o2);
                float bv = __shfl_sync(0xffffffffu, bbv, o2);
                float f = sfc1[o2 * 64 + jj];
                a  += f * vv;
                be += f * bv;
            }
            g_alpha[jj] = a;
            g_beta[jj]  = be + fc1_b[jj];
        }
    }

    // -- phase C: init X and run the 3-layer mode chain --
    {
        float xr = sXr[b] * INV_N2;
        float xi = sXi[b] * INV_N2;
        float w0 = fc0_w[o];
        X[b][o] = make_float2(w0 * xr + (dc ? fc0_b[o] : 0.f), w0 * xi);
    }
    __syncthreads();

    for (int d = 0; d < 3; d++) {
        float yr = 0.f, yi = 0.f;
#pragma unroll
        for (int c = 0; c < 16; c++) {
            float wr = swr[(d * 16 + c) * 16 + o], wim = swi[(d * 16 + c) * 16 + o];
            float xr = X[b][c].x, xi = X[b][c].y;
            yr += xr * wr - xi * wim;
            yi += xr * wim + xi * wr;
        }
        if (d == 0) Y0[b][o] = make_float2(yr, yi);
        else if (d == 1) Y1[b][o] = make_float2(yr, yi);
        else Y2[b][o] = make_float2(yr, yi);

        // band-fold: DFT of the inverse transform of the kept band
        float gyr = yr, gyi = yi;
        if (ky == 0) {
            if (kx == 0) gyi = 0.f;
            else { gyr *= 0.5f; gyi *= 0.5f; }
        }
        float nr = gyr, ni = gyi;
#pragma unroll
        for (int c = 0; c < 16; c++) {
            float cw = scw[d * 256 + o * 16 + c];
            nr += cw * X[b][c].x;
            ni += cw * X[b][c].y;
        }
        if (dc) nr += conv_b[d * 16 + o];
        __syncthreads();
        X[b][o] = make_float2(nr, ni);
        __syncthreads();
    }

    // Ycomb = Y2 + C2*(Y1 + C1*Y0)
    {
        float tr = Y1[b][o].x, ti = Y1[b][o].y;
#pragma unroll
        for (int c = 0; c < 16; c++) {
            float cw = scw[1 * 256 + o * 16 + c];
            tr += cw * Y0[b][c].x;
            ti += cw * Y0[b][c].y;
        }
        __syncthreads();
        X[b][o] = make_float2(tr, ti);
        __syncthreads();
        float yr = Y2[b][o].x, yi = Y2[b][o].y;
#pragma unroll
        for (int c = 0; c < 16; c++) {
            float cw = scw[2 * 256 + o * 16 + c];
            yr += cw * X[b][c].x;
            yi += cw * X[b][c].y;
        }
        __syncthreads();
        Y0[b][o] = make_float2(yr, yi);   // Y0 := Ycomb
        __syncthreads();
    }

    // fold fc1: Z[b][j] = sum_o fc1_w[o][j] * Ycomb[b][o]; layout [b][j][ky][kx]
#pragma unroll
    for (int r = 0; r < 4; r++) {
        int j = (t & 15) + 16 * r;
        float zr = 0.f, zi = 0.f;
#pragma unroll
        for (int o2 = 0; o2 < 16; o2++) {
            float f = sfc1[o2 * 64 + j];
            zr += f * Y0[b][o2].x;
            zi += f * Y0[b][o2].y;
        }
        g_Z[(((size_t)b * HID + j) * 8 + ky) * 8 + kx] = make_float2(zr, zi);
    }
}

// ============ stage 3: fused per-pixel evaluation (E/O split + f32x2) =========
__global__ void __launch_bounds__(128) k_main(const float* __restrict__ x,
                                              const float* __restrict__ fc2_w,
                                              const float* __restrict__ fc2_b,
                                              float* __restrict__ out) {
    const int b = blockIdx.y, h = blockIdx.x;
    const int tid = threadIdx.x;

    // slots 0-5: E(ky=2,4,6 cos/sin); 6-13: O(ky=1,3,5,7); 14 alpha; 15 beta+c0
    __shared__ __align__(16) u64 tab[64][16];
    __shared__ u64 s_fc2p[64];

    // row phases e^{+i kx th_h}
    float pc[8], ps[8];
    {
        float s1, c1;
        __sincosf((float)h * TH, &s1, &c1);
        float ck = 1.f, sk = 0.f;
#pragma unroll
        for (int k = 0; k < 8; k++) {
            pc[k] = ck; ps[k] = sk;
            float cn = ck * c1 - sk * s1;
            float sn = sk * c1 + ck * s1;
            ck = cn; sk = sn;
        }
    }

    for (int r = 0; r < 4; r++) {
        int idx = tid + 128 * r;   // j*8 + ky
        int j = idx >> 3, ky = idx & 7;
        const float4* zp = (const float4*)(g_Z + (((size_t)b * HID + j) * 8 + ky) * 8);
        float4 z01 = zp[0], z23 = zp[1], z45 = zp[2], z67 = zp[3];
        float ar, ai;
        ar  = z01.x * pc[0] - z01.y * ps[0];  ai  = z01.x * ps[0] + z01.y * pc[0];
        ar += z01.z * pc[1] - z01.w * ps[1];  ai += z01.z * ps[1] + z01.w * pc[1];
        ar += z23.x * pc[2] - z23.y * ps[2];  ai += z23.x * ps[2] + z23.y * pc[2];
        ar += z23.z * pc[3] - z23.w * ps[3];  ai += z23.z * ps[3] + z23.w * pc[3];
        ar += z45.x * pc[4] - z45.y * ps[4];  ai += z45.x * ps[4] + z45.y * pc[4];
        ar += z45.z * pc[5] - z45.w * ps[5];  ai += z45.z * ps[5] + z45.w * pc[5];
        ar += z67.x * pc[6] - z67.y * ps[6];  ai += z67.x * ps[6] + z67.y * pc[6];
        ar += z67.z * pc[7] - z67.w * ps[7];  ai += z67.z * ps[7] + z67.w * pc[7];

        if (ky == 0) {
            float bc0 = g_beta[j] + ar;      // c0 = Re(A), fold into beta
            float al = g_alpha[j];
            float w2 = fc2_w[j];
            tab[j][14] = pk2(al, al);
            tab[j][15] = pk2(bc0, bc0);
            s_fc2p[j]  = pk2(w2, w2);
        } else {
            float ccos = 2.f * ar, csin = -2.f * ai;
            int slot = (ky & 1) ? (5 + ky) : (ky - 2);
            tab[j][slot]     = pk2(ccos, ccos);
            tab[j][slot + 1] = pk2(csin, csin);
        }
    }

    // per-thread basis for base pixels w0=tid, w1=tid+128 (lanes of f32x2)
    float b0[16], b1[16];
    {
        float s1, c1;
        __sincosf((float)tid * TH, &s1, &c1);
        float ck = 1.f, sk = 0.f;
#pragma unroll
        for (int k = 0; k < 8; k++) {
            b0[2 * k] = ck; b0[2 * k + 1] = sk;
            float cn = ck * c1 - sk * s1;
            float sn = sk * c1 + ck * s1;
            ck = cn; sk = sn;
        }
    }
    {
        float s1, c1;
        __sincosf((float)(tid + 128) * TH, &s1, &c1);
        float ck = 1.f, sk = 0.f;
#pragma unroll
        for (int k = 0; k < 8; k++) {
            b1[2 * k] = ck; b1[2 * k + 1] = sk;
            float cn = ck * c1 - sk * s1;
            float sn = sk * c1 + ck * s1;
            ck = cn; sk = sn;
        }
    }
    u64 bE0 = pk2(b0[4],  b1[4]),  bE1 = pk2(b0[5],  b1[5]);
    u64 bE2 = pk2(b0[8],  b1[8]),  bE3 = pk2(b0[9],  b1[9]);
    u64 bE4 = pk2(b0[12], b1[12]), bE5 = pk2(b0[13], b1[13]);
    u64 bO0 = pk2(b0[2],  b1[2]),  bO1 = pk2(b0[3],  b1[3]);
    u64 bO2 = pk2(b0[6],  b1[6]),  bO3 = pk2(b0[7],  b1[7]);
    u64 bO4 = pk2(b0[10], b1[10]), bO5 = pk2(b0[11], b1[11]);
    u64 bO6 = pk2(b0[14], b1[14]), bO7 = pk2(b0[15], b1[15]);

    const float* xrow = x + ((size_t)b * HH + h) * WW;
    u64 xpa = pk2(xrow[tid],       xrow[tid + 128]);
    u64 xpb = pk2(xrow[tid + 256], xrow[tid + 384]);
    const u64 NEG1 = pk2(-1.f, -1.f);

    __syncthreads();

    u64 acc01 = pk2(0.f, 0.f), acc23 = pk2(0.f, 0.f);
#pragma unroll 2
    for (int j = 0; j < 64; j++) {
        const ulonglong2* tj = (const ulonglong2*)(&tab[j][0]);
        ulonglong2 q0 = tj[0], q1 = tj[1], q2 = tj[2], q3 = tj[3];
        ulonglong2 q4 = tj[4], q5 = tj[5], q6 = tj[6], q7 = tj[7];

        u64 e = mul2(q0.x, bE0);
        e = fma2(q0.y, bE1, e);
        e = fma2(q1.x, bE2, e);
        e = fma2(q1.y, bE3, e);
        e = fma2(q2.x, bE4, e);
        e = fma2(q2.y, bE5, e);

        u64 o = mul2(q3.x, bO0);
        o = fma2(q3.y, bO1, o);
        o = fma2(q4.x, bO2, o);
        o = fma2(q4.y, bO3, o);
        o = fma2(q5.x, bO4, o);
        o = fma2(q5.y, bO5, o);
        o = fma2(q6.x, bO6, o);
        o = fma2(q6.y, bO7, o);

        u64 ba  = fma2(q7.x, xpa, q7.y);
        u64 bb_ = fma2(q7.x, xpb, q7.y);
        u64 ua = add2(ba, add2(e, o));
        u64 ub = add2(bb_, fma2(o, NEG1, e));

        float ua0, ua1, ub0, ub1;
        upk2(ua, ua0, ua1);
        upk2(ub, ub0, ub1);
        float r0 = fmaxf(ua0, 0.f), r1 = fmaxf(ua1, 0.f);
        float r2 = fmaxf(ub0, 0.f), r3 = fmaxf(ub1, 0.f);
        u64 w2p = s_fc2p[j];
        acc01 = fma2(w2p, pk2(r0, r1), acc01);
        acc23 = fma2(w2p, pk2(r2, r3), acc23);
    }

    float a0, a1, a2, a3;
    upk2(acc01, a0, a1);
    upk2(acc23, a2, a3);
    float ob = fc2_b[0];
    float* orow = out + ((size_t)b * HH + h) * WW;
    orow[tid]       = a0 + ob;
    orow[tid + 128] = a1 + ob;
    orow[tid + 256] = a2 + ob;
    orow[tid + 384] = a3 + ob;
}

// ---------------- launch -----------------------------------------------------
extern "C" void kernel_launch(void* const* d_in, const int* in_sizes, int n_in,
                              void* d_out, int out_size) {
    const float* x       = (const float*)d_in[0];
    const float* fc0_w   = (const float*)d_in[1];
    const float* fc0_b   = (const float*)d_in[2];
    const float* spec_wr = (const float*)d_in[3];
    const float* spec_wi = (const float*)d_in[4];
    const float* conv_w  = (const float*)d_in[5];
    const float* conv_b  = (const float*)d_in[6];
    const float* fc1_w   = (const float*)d_in[7];
    const float* fc1_b   = (const float*)d_in[8];
    const float* fc2_w   = (const float*)d_in[9];
    const float* fc2_b   = (const float*)d_in[10];
    float* out = (float*)d_out;

    dim3 grid(HH, NB);
    k_rowdft<<<grid, 256>>>(x);
    k_spectral<<<64, 128>>>(spec_wr, spec_wi, conv_w, conv_b,
                            fc0_w, fc0_b, fc1_w, fc1_b);
    k_main<<<grid, 128>>>(x, fc2_w, fc2_b, out);
}

// round 8
// speedup vs baseline: 1.4021x; 1.4021x over previous
#include <cuda_runtime.h>

#define HH 512
#define WW 512
#define NB 8
#define HID 64
#define TH 0.012271846303085129f   // 2*pi/512
#define INV_N2 3.814697265625e-06f // 1/(512*512)

typedef unsigned long long u64;

// ---------------- scratch (static device globals; no allocation) -------------
__device__ float  g_R2[16 * NB * HH];     // [v][b*512+h], v = 2*ky + (0:re / 1:im)
__device__ float2 g_Z[NB * HID * 8 * 8];  // [b][j][ky][kx]
__device__ float  g_alpha[HID];
__device__ float  g_beta[HID];

// ---------------- f32x2 packed helpers ---------------------------------------
__device__ __forceinline__ u64 pk2(float lo, float hi) {
    u64 r; asm("mov.b64 %0, {%1,%2};" : "=l"(r) : "f"(lo), "f"(hi)); return r;
}
__device__ __forceinline__ void upk2(u64 v, float& lo, float& hi) {
    asm("mov.b64 {%0,%1}, %2;" : "=f"(lo), "=f"(hi) : "l"(v));
}
__device__ __forceinline__ u64 fma2(u64 a, u64 b, u64 c) {
    u64 d; asm("fma.rn.f32x2 %0, %1, %2, %3;" : "=l"(d) : "l"(a), "l"(b), "l"(c)); return d;
}
__device__ __forceinline__ u64 mul2(u64 a, u64 b) {
    u64 d; asm("mul.rn.f32x2 %0, %1, %2;" : "=l"(d) : "l"(a), "l"(b)); return d;
}
__device__ __forceinline__ u64 add2(u64 a, u64 b) {
    u64 d; asm("add.rn.f32x2 %0, %1, %2;" : "=l"(d) : "l"(a), "l"(b)); return d;
}

// ============ stage 1: per-row partial DFT of x (8 modes, radix-4 fold) =======
__global__ void __launch_bounds__(128) k_rowdft(const float* __restrict__ x) {
    const int b = blockIdx.y, h = blockIdx.x;
    const int tid = threadIdx.x;

    __shared__ float sv[128 * 17];
    __shared__ float sp[8 * 17];

    const float* row = x + ((size_t)b * HH + h) * WW;
    float x0 = row[tid], x1 = row[tid + 128], x2 = row[tid + 256], x3 = row[tid + 384];
    float s0 = x0 + x2, sd = x0 - x2;
    float t0 = x1 + x3, td = x1 - x3;
    float u0 = s0 + t0, u2 = s0 - t0;

    float vals[16];
    {
        float s1v, c1v;
        __sincosf((float)tid * TH, &s1v, &c1v);
        float ck = 1.f, sk = 0.f;
#pragma unroll
        for (int k = 0; k < 8; k++) {
            if ((k & 1) == 0) {
                float src = ((k & 3) == 0) ? u0 : u2;
                vals[2 * k]     =  src * ck;
                vals[2 * k + 1] = -src * sk;
            } else {
                float sg = ((k & 3) == 1) ? 1.f : -1.f;
                vals[2 * k]     =  sd * ck - sg * td * sk;
                vals[2 * k + 1] = -sd * sk - sg * td * ck;
            }
            float cn = ck * c1v - sk * s1v;
            float sn = sk * c1v + ck * s1v;
            ck = cn; sk = sn;
        }
    }

#pragma unroll
    for (int i = 0; i < 16; i++) sv[tid * 17 + i] = vals[i];
    __syncthreads();

    {
        int v = tid & 15, g = tid >> 4;   // 8 groups of 16
        float p = 0.f;
#pragma unroll
        for (int i = 0; i < 16; i++) p += sv[(g * 16 + i) * 17 + v];
        sp[g * 17 + v] = p;
    }
    __syncthreads();

    if (tid < 16) {
        float s = 0.f;
#pragma unroll
        for (int g = 0; g < 8; g++) s += sp[g * 17 + tid];
        g_R2[tid * (NB * HH) + b * HH + h] = s;
    }
}

// ============ stage 2: fused column-DFT + mode chain + affine =================
__global__ void __launch_bounds__(128) k_spectral(const float* __restrict__ spec_wr,
                                                  const float* __restrict__ spec_wi,
                                                  const float* __restrict__ conv_w,
                                                  const float* __restrict__ conv_b,
                                                  const float* __restrict__ fc0_w,
                                                  const float* __restrict__ fc0_b,
                                                  const float* __restrict__ fc1_w,
                                                  const float* __restrict__ fc1_b) {
    const int site = blockIdx.x;
    const int kx = site >> 3, ky = site & 7;
    const bool dc = (site == 0);
    const int t = threadIdx.x;
    const int b = t >> 4, o = t & 15;

    __shared__ float swr[768];
    __shared__ float swi[768];
    __shared__ float scw[768];
    __shared__ float sfc1[1024];
    __shared__ float sXr[NB], sXi[NB];
    __shared__ float2 X[NB][16], Y0[NB][16], Y1[NB][16], Y2[NB][16];

    float rwr[6], rwi[6], rcw[6], rf1[8];
#pragma unroll
    for (int q = 0; q < 6; q++) {
        int i = t + 128 * q;
        rwr[q] = spec_wr[(size_t)i * 64 + site];
        rwi[q] = spec_wi[(size_t)i * 64 + site];
        rcw[q] = conv_w[i];
    }
#pragma unroll
    for (int q = 0; q < 8; q++) rf1[q] = fc1_w[t + 128 * q];

    if (t < NB) { sXr[t] = 0.f; sXi[t] = 0.f; }
    __syncthreads();

    {
        const int chunk = t & 15;
        const float* pr = g_R2 + (2 * ky) * (NB * HH) + b * HH;
        const float* pim = g_R2 + (2 * ky + 1) * (NB * HH) + b * HH;
        float c0, s0, cs, ss;
        __sincosf((float)kx * TH * (float)chunk, &s0, &c0);
        __sincosf((float)kx * TH * 16.f, &ss, &cs);
        float ck = c0, sk = s0;
        float vr = 0.f, vi = 0.f;
#pragma unroll 4
        for (int it = 0; it < 32; it++) {
            int h = chunk + 16 * it;
            float rr = pr[h], ri = pim[h];
            vr += rr * ck + ri * sk;
            vi += ri * ck - rr * sk;
            float cn = ck * cs - sk * ss;
            float sn = sk * cs + ck * ss;
            ck = cn; sk = sn;
        }
        atomicAdd(&sXr[b], vr);
        atomicAdd(&sXi[b], vi);
    }

#pragma unroll
    for (int q = 0; q < 6; q++) {
        int i = t + 128 * q;
        swr[i] = rwr[q];
        swi[i] = rwi[q];
        scw[i] = rcw[q];
    }
#pragma unroll
    for (int q = 0; q < 8; q++) sfc1[t + 128 * q] = rf1[q];
    __syncthreads();

    if (dc && t < 32) {
        int oo = t & 15;
        float v = fc0_w[oo], bbv = fc0_b[oo];
        for (int d = 0; d < 3; d++) {
            float sv_ = 0.f, sb_ = 0.f;
#pragma unroll
            for (int c = 0; c < 16; c++) {
                float vv = __shfl_sync(0xffffffffu, v, c);
                float bv = __shfl_sync(0xffffffffu, bbv, c);
                float cw = scw[d * 256 + oo * 16 + c];
                sv_ += cw * vv;
                sb_ += cw * bv;
            }
            v = sv_;
            bbv = sb_ + conv_b[d * 16 + oo];
        }
        for (int jj = t; jj < 64; jj += 32) {
            float a = 0.f, be = 0.f;
#pragma unroll
            for (int o2 = 0; o2 < 16; o2++) {
                float vv = __shfl_sync(0xffffffffu, v, o2);
                float bv = __shfl_sync(0xffffffffu, bbv, o2);
                float f = sfc1[o2 * 64 + jj];
                a  += f * vv;
                be += f * bv;
            }
            g_alpha[jj] = a;
            g_beta[jj]  = be + fc1_b[jj];
        }
    }

    {
        float xr = sXr[b] * INV_N2;
        float xi = sXi[b] * INV_N2;
        float w0 = fc0_w[o];
        X[b][o] = make_float2(w0 * xr + (dc ? fc0_b[o] : 0.f), w0 * xi);
    }
    __syncthreads();

    for (int d = 0; d < 3; d++) {
        float yr = 0.f, yi = 0.f;
#pragma unroll
        for (int c = 0; c < 16; c++) {
            float wr = swr[(d * 16 + c) * 16 + o], wim = swi[(d * 16 + c) * 16 + o];
            float xr = X[b][c].x, xi = X[b][c].y;
            yr += xr * wr - xi * wim;
            yi += xr * wim + xi * wr;
        }
        if (d == 0) Y0[b][o] = make_float2(yr, yi);
        else if (d == 1) Y1[b][o] = make_float2(yr, yi);
        else Y2[b][o] = make_float2(yr, yi);

        float gyr = yr, gyi = yi;
        if (ky == 0) {
            if (kx == 0) gyi = 0.f;
            else { gyr *= 0.5f; gyi *= 0.5f; }
        }
        float nr = gyr, ni = gyi;
#pragma unroll
        for (int c = 0; c < 16; c++) {
            float cw = scw[d * 256 + o * 16 + c];
            nr += cw * X[b][c].x;
            ni += cw * X[b][c].y;
        }
        if (dc) nr += conv_b[d * 16 + o];
        __syncthreads();
        X[b][o] = make_float2(nr, ni);
        __syncthreads();
    }

    {
        float tr = Y1[b][o].x, ti = Y1[b][o].y;
#pragma unroll
        for (int c = 0; c < 16; c++) {
            float cw = scw[1 * 256 + o * 16 + c];
            tr += cw * Y0[b][c].x;
            ti += cw * Y0[b][c].y;
        }
        __syncthreads();
        X[b][o] = make_float2(tr, ti);
        __syncthreads();
        float yr = Y2[b][o].x, yi = Y2[b][o].y;
#pragma unroll
        for (int c = 0; c < 16; c++) {
            float cw = scw[2 * 256 + o * 16 + c];
            yr += cw * X[b][c].x;
            yi += cw * X[b][c].y;
        }
        __syncthreads();
        Y0[b][o] = make_float2(yr, yi);
        __syncthreads();
    }

#pragma unroll
    for (int r = 0; r < 4; r++) {
        int j = (t & 15) + 16 * r;
        float zr = 0.f, zi = 0.f;
#pragma unroll
        for (int o2 = 0; o2 < 16; o2++) {
            float f = sfc1[o2 * 64 + j];
            zr += f * Y0[b][o2].x;
            zi += f * Y0[b][o2].y;
        }
        g_Z[(((size_t)b * HID + j) * 8 + ky) * 8 + kx] = make_float2(zr, zi);
    }
}

// ============ stage 3: per-pixel eval; quarter-wave + (j, j+32) lanes =========
// 64 threads per (b,h); thread covers 8 pixels w = tid + 64m.
// f32x2 lanes hold channel pair (j, j+32); coefficients packed 2-per-u64.
__global__ void __launch_bounds__(64) k_main(const float* __restrict__ x,
                                             const float* __restrict__ fc2_w,
                                             const float* __restrict__ fc2_b,
                                             float* __restrict__ out) {
    const int b = blockIdx.y, h = blockIdx.x;
    const int tid = threadIdx.x;

    // tabf[jp][slot][lane]: slot 0-5 E(ky=2,4,6 cos/sin), 6-13 O(ky=1,3,5,7),
    // 14 alpha, 15 beta+c0; lane 0 = j, lane 1 = j+32.
    __shared__ __align__(16) float tabf[32][16][2];
    __shared__ __align__(8)  float fc2f[32][2];

    // row phases e^{+i kx th_h}
    float pc[8], ps[8];
    {
        float s1, c1;
        __sincosf((float)h * TH, &s1, &c1);
        float ck = 1.f, sk = 0.f;
#pragma unroll
        for (int k = 0; k < 8; k++) {
            pc[k] = ck; ps[k] = sk;
            float cn = ck * c1 - sk * s1;
            float sn = sk * c1 + ck * s1;
            ck = cn; sk = sn;
        }
    }

#pragma unroll
    for (int r = 0; r < 8; r++) {
        int idx = tid + 64 * r;   // j*8 + ky
        int j = idx >> 3, ky = idx & 7;
        const float4* zp = (const float4*)(g_Z + (((size_t)b * HID + j) * 8 + ky) * 8);
        float4 z01 = zp[0], z23 = zp[1], z45 = zp[2], z67 = zp[3];
        float ar, ai;
        ar  = z01.x * pc[0] - z01.y * ps[0];  ai  = z01.x * ps[0] + z01.y * pc[0];
        ar += z01.z * pc[1] - z01.w * ps[1];  ai += z01.z * ps[1] + z01.w * pc[1];
        ar += z23.x * pc[2] - z23.y * ps[2];  ai += z23.x * ps[2] + z23.y * pc[2];
        ar += z23.z * pc[3] - z23.w * ps[3];  ai += z23.z * ps[3] + z23.w * pc[3];
        ar += z45.x * pc[4] - z45.y * ps[4];  ai += z45.x * ps[4] + z45.y * pc[4];
        ar += z45.z * pc[5] - z45.w * ps[5];  ai += z45.z * ps[5] + z45.w * pc[5];
        ar += z67.x * pc[6] - z67.y * ps[6];  ai += z67.x * ps[6] + z67.y * pc[6];
        ar += z67.z * pc[7] - z67.w * ps[7];  ai += z67.z * ps[7] + z67.w * pc[7];

        int jp = j & 31, ln = j >> 5;
        if (ky == 0) {
            tabf[jp][14][ln] = g_alpha[j];
            tabf[jp][15][ln] = g_beta[j] + ar;   // c0 = Re(A)
            fc2f[jp][ln]     = fc2_w[j];
        } else {
            int slot = (ky & 1) ? (5 + ky) : (ky - 2);
            tabf[jp][slot][ln]     = 2.f * ar;
            tabf[jp][slot + 1][ln] = -2.f * ai;
        }
    }

    // basis for base pixels wA=tid, wB=tid+64 (broadcast to both lanes)
    float b0[16], b1[16];
    {
        float s1, c1;
        __sincosf((float)tid * TH, &s1, &c1);
        float ck = 1.f, sk = 0.f;
#pragma unroll
        for (int k = 0; k < 8; k++) {
            b0[2 * k] = ck; b0[2 * k + 1] = sk;
            float cn = ck * c1 - sk * s1;
            float sn = sk * c1 + ck * s1;
            ck = cn; sk = sn;
        }
    }
    {
        float s1, c1;
        __sincosf((float)(tid + 64) * TH, &s1, &c1);
        float ck = 1.f, sk = 0.f;
#pragma unroll
        for (int k = 0; k < 8; k++) {
            b1[2 * k] = ck; b1[2 * k + 1] = sk;
            float cn = ck * c1 - sk * s1;
            float sn = sk * c1 + ck * s1;
            ck = cn; sk = sn;
        }
    }
    // E: ky=2,4,6 (cos,sin); O: ky=1,3,5,7 (cos,sin) — broadcast u64
    u64 AE0 = pk2(b0[4],  b0[4]),  AE1 = pk2(b0[5],  b0[5]);
    u64 AE2 = pk2(b0[8],  b0[8]),  AE3 = pk2(b0[9],  b0[9]);
    u64 AE4 = pk2(b0[12], b0[12]), AE5 = pk2(b0[13], b0[13]);
    u64 AO0 = pk2(b0[2],  b0[2]),  AO1 = pk2(b0[3],  b0[3]);
    u64 AO2 = pk2(b0[6],  b0[6]),  AO3 = pk2(b0[7],  b0[7]);
    u64 AO4 = pk2(b0[10], b0[10]), AO5 = pk2(b0[11], b0[11]);
    u64 AO6 = pk2(b0[14], b0[14]), AO7 = pk2(b0[15], b0[15]);
    u64 BE0 = pk2(b1[4],  b1[4]),  BE1 = pk2(b1[5],  b1[5]);
    u64 BE2 = pk2(b1[8],  b1[8]),  BE3 = pk2(b1[9],  b1[9]);
    u64 BE4 = pk2(b1[12], b1[12]), BE5 = pk2(b1[13], b1[13]);
    u64 BO0 = pk2(b1[2],  b1[2]),  BO1 = pk2(b1[3],  b1[3]);
    u64 BO2 = pk2(b1[6],  b1[6]),  BO3 = pk2(b1[7],  b1[7]);
    u64 BO4 = pk2(b1[10], b1[10]), BO5 = pk2(b1[11], b1[11]);
    u64 BO6 = pk2(b1[14], b1[14]), BO7 = pk2(b1[15], b1[15]);

    const float* xrow = x + ((size_t)b * HH + h) * WW;
    u64 xb[8];
#pragma unroll
    for (int m = 0; m < 8; m++) {
        float xv = xrow[tid + 64 * m];
        xb[m] = pk2(xv, xv);
    }
    const u64 NEG1 = pk2(-1.f, -1.f);

    __syncthreads();

    u64 acc[8];
#pragma unroll
    for (int m = 0; m < 8; m++) acc[m] = pk2(0.f, 0.f);

#pragma unroll 1
    for (int jp = 0; jp < 32; jp++) {
        const ulonglong2* tj = (const ulonglong2*)(&tabf[jp][0][0]);
        ulonglong2 q0 = tj[0], q1 = tj[1], q2 = tj[2], q3 = tj[3];
        ulonglong2 q4 = tj[4], q5 = tj[5], q6 = tj[6], q7 = tj[7];
        u64 w2p = *(const u64*)(&fc2f[jp][0]);

        // ---- family A: pixels m=0 (w), m=4 (+256), m=2 (+128), m=6 (+384) ----
        u64 ePA = fma2(q1.y, AE3, mul2(q1.x, AE2));                    // ky=4
        u64 eMA = fma2(q2.y, AE5, fma2(q2.x, AE4,
                  fma2(q0.y, AE1, mul2(q0.x, AE0))));                  // ky=2,6
        u64 oA  = fma2(q6.y, AO7, fma2(q6.x, AO6, fma2(q5.y, AO5,
                  fma2(q5.x, AO4, fma2(q4.y, AO3, fma2(q4.x, AO2,
                  fma2(q3.y, AO1, mul2(q3.x, AO0))))))));
        u64 oPA = fma2(q6.x, AO7, fma2(q5.y, AO4,
                  fma2(q4.x, AO3, mul2(q3.y, AO0))));
        u64 oMA = fma2(q6.y, AO6, fma2(q5.x, AO5,
                  fma2(q4.y, AO2, mul2(q3.x, AO1))));
        u64 eA  = add2(ePA, eMA);
        u64 eA2 = fma2(eMA, NEG1, ePA);     // eP - eM (basis at w+128)
        {
            u64 ba = fma2(q7.x, xb[0], q7.y);
            u64 t0_ = add2(ba, eA);
            u64 u_  = add2(t0_, oA);
            float lo, hi; upk2(u_, lo, hi);
            acc[0] = fma2(w2p, pk2(fmaxf(lo, 0.f), fmaxf(hi, 0.f)), acc[0]);
        }
        {
            u64 ba = fma2(q7.x, xb[4], q7.y);
            u64 t0_ = add2(ba, eA);
            u64 u_  = fma2(oA, NEG1, t0_);
            float lo, hi; upk2(u_, lo, hi);
            acc[4] = fma2(w2p, pk2(fmaxf(lo, 0.f), fmaxf(hi, 0.f)), acc[4]);
        }
        {
            u64 ba = fma2(q7.x, xb[2], q7.y);
            u64 t0_ = add2(add2(ba, eA2), oPA);
            u64 u_  = fma2(oMA, NEG1, t0_);
            float lo, hi; upk2(u_, lo, hi);
            acc[2] = fma2(w2p, pk2(fmaxf(lo, 0.f), fmaxf(hi, 0.f)), acc[2]);
        }
        {
            u64 ba = fma2(q7.x, xb[6], q7.y);
            u64 t0_ = fma2(oPA, NEG1, add2(ba, eA2));
            u64 u_  = add2(t0_, oMA);
            float lo, hi; upk2(u_, lo, hi);
            acc[6] = fma2(w2p, pk2(fmaxf(lo, 0.f), fmaxf(hi, 0.f)), acc[6]);
        }

        // ---- family B: pixels m=1 (w+64), m=5, m=3, m=7 ----
        u64 ePB = fma2(q1.y, BE3, mul2(q1.x, BE2));
        u64 eMB = fma2(q2.y, BE5, fma2(q2.x, BE4,
                  fma2(q0.y, BE1, mul2(q0.x, BE0))));
        u64 oB  = fma2(q6.y, BO7, fma2(q6.x, BO6, fma2(q5.y, BO5,
                  fma2(q5.x, BO4, fma2(q4.y, BO3, fma2(q4.x, BO2,
                  fma2(q3.y, BO1, mul2(q3.x, BO0))))))));
        u64 oPB = fma2(q6.x, BO7, fma2(q5.y, BO4,
                  fma2(q4.x, BO3, mul2(q3.y, BO0))));
        u64 oMB = fma2(q6.y, BO6, fma2(q5.x, BO5,
                  fma2(q4.y, BO2, mul2(q3.x, BO1))));
        u64 eB  = add2(ePB, eMB);
        u64 eB2 = fma2(eMB, NEG1, ePB);
        {
            u64 ba = fma2(q7.x, xb[1], q7.y);
            u64 t0_ = add2(ba, eB);
            u64 u_  = add2(t0_, oB);
            float lo, hi; upk2(u_, lo, hi);
            acc[1] = fma2(w2p, pk2(fmaxf(lo, 0.f), fmaxf(hi, 0.f)), acc[1]);
        }
        {
            u64 ba = fma2(q7.x, xb[5], q7.y);
            u64 t0_ = add2(ba, eB);
            u64 u_  = fma2(oB, NEG1, t0_);
            float lo, hi; upk2(u_, lo, hi);
            acc[5] = fma2(w2p, pk2(fmaxf(lo, 0.f), fmaxf(hi, 0.f)), acc[5]);
        }
        {
            u64 ba = fma2(q7.x, xb[3], q7.y);
            u64 t0_ = add2(add2(ba, eB2), oPB);
            u64 u_  = fma2(oMB, NEG1, t0_);
            float lo, hi; upk2(u_, lo, hi);
            acc[3] = fma2(w2p, pk2(fmaxf(lo, 0.f), fmaxf(hi, 0.f)), acc[3]);
        }
        {
            u64 ba = fma2(q7.x, xb[7], q7.y);
            u64 t0_ = fma2(oPB, NEG1, add2(ba, eB2));
            u64 u_  = add2(t0_, oMB);
            float lo, hi; upk2(u_, lo, hi);
            acc[7] = fma2(w2p, pk2(fmaxf(lo, 0.f), fmaxf(hi, 0.f)), acc[7]);
        }
    }

    float ob = fc2_b[0];
    float* orow = out + ((size_t)b * HH + h) * WW;
#pragma unroll
    for (int m = 0; m < 8; m++) {
        float lo, hi;
        upk2(acc[m], lo, hi);
        orow[tid + 64 * m] = lo + hi + ob;
    }
}

// ---------------- launch -----------------------------------------------------
extern "C" void kernel_launch(void* const* d_in, const int* in_sizes, int n_in,
                              void* d_out, int out_size) {
    const float* x       = (const float*)d_in[0];
    const float* fc0_w   = (const float*)d_in[1];
    const float* fc0_b   = (const float*)d_in[2];
    const float* spec_wr = (const float*)d_in[3];
    const float* spec_wi = (const float*)d_in[4];
    const float* conv_w  = (const float*)d_in[5];
    const float* conv_b  = (const float*)d_in[6];
    const float* fc1_w   = (const float*)d_in[7];
    const float* fc1_b   = (const float*)d_in[8];
    const float* fc2_w   = (const float*)d_in[9];
    const float* fc2_b   = (const float*)d_in[10];
    float* out = (float*)d_out;

    dim3 grid(HH, NB);
    k_rowdft<<<grid, 128>>>(x);
    k_spectral<<<64, 128>>>(spec_wr, spec_wi, conv_w, conv_b,
                            fc0_w, fc0_b, fc1_w, fc1_b);
    k_main<<<grid, 64>>>(x, fc2_w, fc2_b, out);
}